// round 2
// baseline (speedup 1.0000x reference)
#include <cuda_runtime.h>
#include <math.h>

// PillarFeatureNet fused kernel.
// features: (N, 32, 4) f32; num_points: (N,) i32; coors: (N,4) i32 [b,z,cy,cx]
// W: (63,9) f32; gamma/beta/running_mean/running_var: (63,) f32
// out: (N, 64) f32  = [max over points of relu(BN(feats@W^T)) | num_points]

#define MPTS 32
#define WARPS_PER_BLOCK 8
#define THREADS (WARPS_PER_BLOCK * 32)
#define GRID_BLOCKS 1184

__global__ __launch_bounds__(THREADS)
void pfn_kernel(const float4* __restrict__ feats,
                const int*    __restrict__ num_points,
                const int4*   __restrict__ coors,
                const float*  __restrict__ W,
                const float*  __restrict__ gma,
                const float*  __restrict__ bta,
                const float*  __restrict__ rmean,
                const float*  __restrict__ rvar,
                float* __restrict__ out, int N)
{
    constexpr float VX = 0.16f, VY = 0.16f;
    constexpr float X_OFF = 0.08f;       // VX/2 + 0.0
    constexpr float Y_OFF = -39.6f;      // VY/2 + (-39.68)
    constexpr float BN_EPS = 1e-3f;

    __shared__ float4 sf[WARPS_PER_BLOCK][MPTS];

    const int lane = threadIdx.x & 31;
    const int warp = threadIdx.x >> 5;

    // ---- fold weights + BN once per warp: outputs u0 = lane, u1 = lane+32 ----
    const int u0 = lane;
    const int u1 = lane + 32;

    float ws0a, ws1a, ws2a, ws3a, wm4a, wm5a, wm6a, wm7a, wm8a, ba;
    float ws0b = 0.f, ws1b = 0.f, ws2b = 0.f, ws3b = 0.f;
    float wm4b = 0.f, wm5b = 0.f, wm6b = 0.f, wm7b = 0.f, wm8b = 0.f, bb = 0.f;
    {
        const float inv = gma[u0] / sqrtf(rvar[u0] + BN_EPS);
        ba = bta[u0] - rmean[u0] * inv;
        const float* w = W + u0 * 9;
        const float w0 = w[0], w1 = w[1], w2 = w[2], w3 = w[3], w4 = w[4];
        const float w5 = w[5], w6 = w[6], w7 = w[7], w8 = w[8];
        ws0a = (w0 + w4 + w7) * inv;
        ws1a = (w1 + w5 + w8) * inv;
        ws2a = (w2 + w6) * inv;
        ws3a = w3 * inv;
        wm4a = w4 * inv; wm5a = w5 * inv; wm6a = w6 * inv;
        wm7a = w7 * inv; wm8a = w8 * inv;
    }
    if (u1 < 63) {
        const float inv = gma[u1] / sqrtf(rvar[u1] + BN_EPS);
        bb = bta[u1] - rmean[u1] * inv;
        const float* w = W + u1 * 9;
        const float w0 = w[0], w1 = w[1], w2 = w[2], w3 = w[3], w4 = w[4];
        const float w5 = w[5], w6 = w[6], w7 = w[7], w8 = w[8];
        ws0b = (w0 + w4 + w7) * inv;
        ws1b = (w1 + w5 + w8) * inv;
        ws2b = (w2 + w6) * inv;
        ws3b = w3 * inv;
        wm4b = w4 * inv; wm5b = w5 * inv; wm6b = w6 * inv;
        wm7b = w7 * inv; wm8b = w8 * inv;
    }

    const int stride = gridDim.x * WARPS_PER_BLOCK;
    for (int n = blockIdx.x * WARPS_PER_BLOCK + warp; n < N; n += stride) {
        // each lane loads one point: coalesced 512B per warp
        const float4 f = feats[n * MPTS + lane];
        sf[warp][lane] = f;

        // pillar xyz sum over ALL 32 points (reference sums unmasked)
        float sx = f.x, sy = f.y, sz = f.z;
        #pragma unroll
        for (int off = 16; off; off >>= 1) {
            sx += __shfl_xor_sync(0xffffffffu, sx, off);
            sy += __shfl_xor_sync(0xffffffffu, sy, off);
            sz += __shfl_xor_sync(0xffffffffu, sz, off);
        }

        const int  np = num_points[n];      // uniform load per warp
        const int4 cc = coors[n];           // [b, z, cy, cx]
        const float rnp = 1.0f / (float)np;
        const float mx = sx * rnp, my = sy * rnp, mz = sz * rnp;
        const float ox = (float)cc.w * VX + X_OFF;
        const float oy = (float)cc.z * VY + Y_OFF;

        // per-pillar constant per output (bias + pillar-dependent part folded)
        const float c0 = ba - (mx * wm4a + my * wm5a + mz * wm6a + ox * wm7a + oy * wm8a);
        const float c1 = bb - (mx * wm4b + my * wm5b + mz * wm6b + ox * wm7b + oy * wm8b);

        // masked (padded) points contribute exactly the BN bias; present iff np < 32
        float r0 = (np < MPTS) ? ba : -INFINITY;
        float r1 = (np < MPTS) ? bb : -INFINITY;

        __syncwarp();   // staging visible to all lanes
        #pragma unroll 4
        for (int m = 0; m < np; ++m) {
            const float4 p = sf[warp][m];   // broadcast LDS.128
            const float d0 = fmaf(p.x, ws0a, fmaf(p.y, ws1a, fmaf(p.z, ws2a, fmaf(p.w, ws3a, c0))));
            const float d1 = fmaf(p.x, ws0b, fmaf(p.y, ws1b, fmaf(p.z, ws2b, fmaf(p.w, ws3b, c1))));
            r0 = fmaxf(r0, d0);
            r1 = fmaxf(r1, d1);
        }
        __syncwarp();   // reads done before next iteration overwrites sf

        // relu(max(x)) == max(relu(x)) since relu is monotone
        float* o = out + (size_t)n * 64;
        o[u0] = fmaxf(r0, 0.0f);
        if (u1 < 63) o[u1] = fmaxf(r1, 0.0f);
        else         o[63] = (float)np;     // lane 31 writes the num_points column
    }
}

extern "C" void kernel_launch(void* const* d_in, const int* in_sizes, int n_in,
                              void* d_out, int out_size)
{
    const float* features  = (const float*)d_in[0];
    const int*   num_pts   = (const int*)  d_in[1];
    const int*   coors     = (const int*)  d_in[2];
    const float* W         = (const float*)d_in[3];
    const float* gma       = (const float*)d_in[4];
    const float* bta       = (const float*)d_in[5];
    const float* rmean     = (const float*)d_in[6];
    const float* rvar      = (const float*)d_in[7];

    int N = in_sizes[1];                     // num_points element count == N pillars
    if (N <= 0 || N != in_sizes[0] / (MPTS * 4)) {
        // defensive: derive from features size if ordering ever differs
        N = in_sizes[0] / (MPTS * 4);
    }

    pfn_kernel<<<GRID_BLOCKS, THREADS>>>(
        (const float4*)features, num_pts, (const int4*)coors,
        W, gma, bta, rmean, rvar, (float*)d_out, N);
}

// round 3
// speedup vs baseline: 1.0107x; 1.0107x over previous
#include <cuda_runtime.h>
#include <math.h>

// PillarFeatureNet fused kernel — f32x2-packed, SoA-staged, software-pipelined.
// features: (N, 32, 4) f32; num_points: (N,) i32; coors: (N,4) i32 [b,z,cy,cx]
// W: (63,9) f32; gamma/beta/running_mean/running_var: (63,) f32
// out: (N, 64) f32  = [max over points of relu(BN(feats@W^T)) | num_points]

#define MPTS 32
#define WARPS_PER_BLOCK 8
#define THREADS (WARPS_PER_BLOCK * 32)
#define GRID_BLOCKS 592

typedef unsigned long long ull;

__device__ __forceinline__ ull fma2(ull a, ull b, ull c) {
    ull d; asm("fma.rn.f32x2 %0,%1,%2,%3;" : "=l"(d) : "l"(a), "l"(b), "l"(c)); return d;
}
__device__ __forceinline__ ull dup2(float v) {
    ull d; asm("mov.b64 %0,{%1,%1};" : "=l"(d) : "f"(v)); return d;
}
__device__ __forceinline__ float2 unpk(ull p) {
    float lo, hi; asm("mov.b64 {%0,%1},%2;" : "=f"(lo), "=f"(hi) : "l"(p));
    return make_float2(lo, hi);
}

__global__ __launch_bounds__(THREADS)
void pfn_kernel(const float4* __restrict__ feats,
                const int*    __restrict__ num_points,
                const int4*   __restrict__ coors,
                const float*  __restrict__ W,
                const float*  __restrict__ gma,
                const float*  __restrict__ bta,
                const float*  __restrict__ rmean,
                const float*  __restrict__ rvar,
                float* __restrict__ out, int N)
{
    constexpr float VX = 0.16f, VY = 0.16f;
    constexpr float X_OFF = 0.08f;       // VX/2 + 0.0
    constexpr float Y_OFF = -39.6f;      // VY/2 + (-39.68)
    constexpr float BN_EPS = 1e-3f;

    // SoA staging: [warp][buf][component][point], double-buffered. 8 KB total.
    __shared__ float sbuf[WARPS_PER_BLOCK][2][4][MPTS];

    const int lane = threadIdx.x & 31;
    const int warp = threadIdx.x >> 5;

    // ---- fold weights + BN once per warp: outputs u0 = lane, u1 = lane+32 ----
    const int u0 = lane;
    const int u1 = lane + 32;

    float wm4a, wm5a, wm6a, wm7a, wm8a, ba;
    float wm4b = 0.f, wm5b = 0.f, wm6b = 0.f, wm7b = 0.f, wm8b = 0.f, bb = 0.f;
    ull wsa0, wsa1, wsa2, wsa3;          // duplicated f32x2 weight pairs, output u0
    ull wsb0 = 0, wsb1 = 0, wsb2 = 0, wsb3 = 0;  // output u1
    float ws0a_s, ws1a_s, ws2a_s, ws3a_s;         // scalar copies for tail
    float ws0b_s = 0.f, ws1b_s = 0.f, ws2b_s = 0.f, ws3b_s = 0.f;
    {
        const float inv = gma[u0] / sqrtf(rvar[u0] + BN_EPS);
        ba = bta[u0] - rmean[u0] * inv;
        const float* w = W + u0 * 9;
        const float w0 = w[0], w1 = w[1], w2 = w[2], w3 = w[3], w4 = w[4];
        const float w5 = w[5], w6 = w[6], w7 = w[7], w8 = w[8];
        ws0a_s = (w0 + w4 + w7) * inv;
        ws1a_s = (w1 + w5 + w8) * inv;
        ws2a_s = (w2 + w6) * inv;
        ws3a_s = w3 * inv;
        wsa0 = dup2(ws0a_s); wsa1 = dup2(ws1a_s); wsa2 = dup2(ws2a_s); wsa3 = dup2(ws3a_s);
        wm4a = w4 * inv; wm5a = w5 * inv; wm6a = w6 * inv;
        wm7a = w7 * inv; wm8a = w8 * inv;
    }
    if (u1 < 63) {
        const float inv = gma[u1] / sqrtf(rvar[u1] + BN_EPS);
        bb = bta[u1] - rmean[u1] * inv;
        const float* w = W + u1 * 9;
        const float w0 = w[0], w1 = w[1], w2 = w[2], w3 = w[3], w4 = w[4];
        const float w5 = w[5], w6 = w[6], w7 = w[7], w8 = w[8];
        ws0b_s = (w0 + w4 + w7) * inv;
        ws1b_s = (w1 + w5 + w8) * inv;
        ws2b_s = (w2 + w6) * inv;
        ws3b_s = w3 * inv;
        wsb0 = dup2(ws0b_s); wsb1 = dup2(ws1b_s); wsb2 = dup2(ws2b_s); wsb3 = dup2(ws3b_s);
        wm4b = w4 * inv; wm5b = w5 * inv; wm6b = w6 * inv;
        wm7b = w7 * inv; wm8b = w8 * inv;
    }

    const int stride = gridDim.x * WARPS_PER_BLOCK;
    int n = blockIdx.x * WARPS_PER_BLOCK + warp;
    if (n >= N) return;

    // ---- software pipeline: prime first pillar's loads ----
    float4 f  = feats[(size_t)n * MPTS + lane];
    int    np = num_points[n];
    int4   cc = coors[n];
    int buf = 0;

    while (true) {
        const int n_next = n + stride;

        // stage current pillar (SoA, conflict-free: lane -> bank lane)
        sbuf[warp][buf][0][lane] = f.x;
        sbuf[warp][buf][1][lane] = f.y;
        sbuf[warp][buf][2][lane] = f.z;
        sbuf[warp][buf][3][lane] = f.w;

        // prefetch next pillar (hidden under butterfly + inner loop)
        float4 f_nx; int np_nx = 1; int4 cc_nx;
        const bool have_next = (n_next < N);
        if (have_next) {
            f_nx  = feats[(size_t)n_next * MPTS + lane];
            np_nx = num_points[n_next];
            cc_nx = coors[n_next];
        }

        // pillar xyz sum over ALL 32 points (reference sums unmasked)
        float sx = f.x, sy = f.y, sz = f.z;
        #pragma unroll
        for (int off = 16; off; off >>= 1) {
            sx += __shfl_xor_sync(0xffffffffu, sx, off);
            sy += __shfl_xor_sync(0xffffffffu, sy, off);
            sz += __shfl_xor_sync(0xffffffffu, sz, off);
        }

        const float rnp = 1.0f / (float)np;
        const float mx = sx * rnp, my = sy * rnp, mz = sz * rnp;
        const float ox = (float)cc.w * VX + X_OFF;
        const float oy = (float)cc.z * VY + Y_OFF;

        // per-pillar constant per output
        const float c0 = ba - (mx * wm4a + my * wm5a + mz * wm6a + ox * wm7a + oy * wm8a);
        const float c1 = bb - (mx * wm4b + my * wm5b + mz * wm6b + ox * wm7b + oy * wm8b);
        const ull c0p = dup2(c0);
        const ull c1p = dup2(c1);

        // padded points contribute exactly the BN bias; present iff np < 32
        float r0 = (np < MPTS) ? ba : -INFINITY;
        float r1 = (np < MPTS) ? bb : -INFINITY;

        __syncwarp();   // staging visible to all lanes

        const ulonglong2* xs2 = (const ulonglong2*)sbuf[warp][buf][0];
        const ulonglong2* ys2 = (const ulonglong2*)sbuf[warp][buf][1];
        const ulonglong2* zs2 = (const ulonglong2*)sbuf[warp][buf][2];
        const ulonglong2* ws2 = (const ulonglong2*)sbuf[warp][buf][3];

        const int nfull = np >> 2;
        for (int c = 0; c < nfull; ++c) {
            const ulonglong2 X = xs2[c];   // {x0,x1},{x2,x3}
            const ulonglong2 Y = ys2[c];
            const ulonglong2 Z = zs2[c];
            const ulonglong2 Wv = ws2[c];
            const ull dA0 = fma2(X.x, wsa0, fma2(Y.x, wsa1, fma2(Z.x, wsa2, fma2(Wv.x, wsa3, c0p))));
            const ull dA1 = fma2(X.y, wsa0, fma2(Y.y, wsa1, fma2(Z.y, wsa2, fma2(Wv.y, wsa3, c0p))));
            const ull dB0 = fma2(X.x, wsb0, fma2(Y.x, wsb1, fma2(Z.x, wsb2, fma2(Wv.x, wsb3, c1p))));
            const ull dB1 = fma2(X.y, wsb0, fma2(Y.y, wsb1, fma2(Z.y, wsb2, fma2(Wv.y, wsb3, c1p))));
            const float2 a0 = unpk(dA0), a1 = unpk(dA1);
            const float2 b0 = unpk(dB0), b1 = unpk(dB1);
            r0 = fmaxf(r0, fmaxf(fmaxf(a0.x, a0.y), fmaxf(a1.x, a1.y)));
            r1 = fmaxf(r1, fmaxf(fmaxf(b0.x, b0.y), fmaxf(b1.x, b1.y)));
        }
        const int rem = np & 3;
        if (rem) {                        // partial last chunk, predicated max
            const int c = nfull;
            const ulonglong2 X = xs2[c];
            const ulonglong2 Y = ys2[c];
            const ulonglong2 Z = zs2[c];
            const ulonglong2 Wv = ws2[c];
            const ull dA0 = fma2(X.x, wsa0, fma2(Y.x, wsa1, fma2(Z.x, wsa2, fma2(Wv.x, wsa3, c0p))));
            const ull dA1 = fma2(X.y, wsa0, fma2(Y.y, wsa1, fma2(Z.y, wsa2, fma2(Wv.y, wsa3, c0p))));
            const ull dB0 = fma2(X.x, wsb0, fma2(Y.x, wsb1, fma2(Z.x, wsb2, fma2(Wv.x, wsb3, c1p))));
            const ull dB1 = fma2(X.y, wsb0, fma2(Y.y, wsb1, fma2(Z.y, wsb2, fma2(Wv.y, wsb3, c1p))));
            const float2 a0 = unpk(dA0), a1 = unpk(dA1);
            const float2 b0 = unpk(dB0), b1 = unpk(dB1);
            r0 = fmaxf(r0, a0.x);  r1 = fmaxf(r1, b0.x);            // rem >= 1
            if (rem > 1) { r0 = fmaxf(r0, a0.y); r1 = fmaxf(r1, b0.y); }
            if (rem > 2) { r0 = fmaxf(r0, a1.x); r1 = fmaxf(r1, b1.x); }
        }

        // relu(max(x)) == max(relu(x)) since relu is monotone
        float* o = out + (size_t)n * 64;
        o[u0] = fmaxf(r0, 0.0f);
        if (u1 < 63) o[u1] = fmaxf(r1, 0.0f);
        else         o[63] = (float)np;     // lane 31 writes num_points column

        if (!have_next) break;
        n = n_next; f = f_nx; np = np_nx; cc = cc_nx; buf ^= 1;
    }
}

extern "C" void kernel_launch(void* const* d_in, const int* in_sizes, int n_in,
                              void* d_out, int out_size)
{
    const float* features  = (const float*)d_in[0];
    const int*   num_pts   = (const int*)  d_in[1];
    const int*   coors     = (const int*)  d_in[2];
    const float* W         = (const float*)d_in[3];
    const float* gma       = (const float*)d_in[4];
    const float* bta       = (const float*)d_in[5];
    const float* rmean     = (const float*)d_in[6];
    const float* rvar      = (const float*)d_in[7];

    int N = in_sizes[1];                     // num_points element count == N pillars
    if (N <= 0 || N != in_sizes[0] / (MPTS * 4)) {
        N = in_sizes[0] / (MPTS * 4);        // defensive fallback
    }

    pfn_kernel<<<GRID_BLOCKS, THREADS>>>(
        (const float4*)features, num_pts, (const int4*)coors,
        W, gma, bta, rmean, rvar, (float*)d_out, N);
}

// round 8
// speedup vs baseline: 1.0557x; 1.0446x over previous
#include <cuda_runtime.h>
#include <math.h>

// PillarFeatureNet fused kernel — R4: additive-constant hoist, NaN-masked tail,
// fully unrolled f32x2 inner loop, low-register single-buffer design.
// features: (N, 32, 4) f32; num_points: (N,) i32; coors: (N,4) i32 [b,z,cy,cx]
// W: (63,9) f32; gamma/beta/running_mean/running_var: (63,) f32
// out: (N, 64) f32  = [max over points of relu(BN(feats@W^T)) | num_points]

#define MPTS 32
#define WARPS_PER_BLOCK 4
#define THREADS (WARPS_PER_BLOCK * 32)
#define GRID_BLOCKS 1184

typedef unsigned long long ull;

__device__ __forceinline__ ull fma2(ull a, ull b, ull c) {
    ull d; asm("fma.rn.f32x2 %0,%1,%2,%3;" : "=l"(d) : "l"(a), "l"(b), "l"(c)); return d;
}
__device__ __forceinline__ ull mul2(ull a, ull b) {
    ull d; asm("mul.rn.f32x2 %0,%1,%2;" : "=l"(d) : "l"(a), "l"(b)); return d;
}
__device__ __forceinline__ ull add2(ull a, ull b) {
    ull d; asm("add.rn.f32x2 %0,%1,%2;" : "=l"(d) : "l"(a), "l"(b)); return d;
}
__device__ __forceinline__ ull dup2(float v) {
    ull d; asm("mov.b64 %0,{%1,%1};" : "=l"(d) : "f"(v)); return d;
}
__device__ __forceinline__ ull pack2(float lo, float hi) {
    ull d; asm("mov.b64 %0,{%1,%2};" : "=l"(d) : "f"(lo), "f"(hi)); return d;
}
__device__ __forceinline__ float2 unpk(ull p) {
    float lo, hi; asm("mov.b64 {%0,%1},%2;" : "=f"(lo), "=f"(hi) : "l"(p));
    return make_float2(lo, hi);
}

__global__ __launch_bounds__(THREADS, 8)
void pfn_kernel(const float4* __restrict__ feats,
                const int*    __restrict__ num_points,
                const int4*   __restrict__ coors,
                const float*  __restrict__ W,
                const float*  __restrict__ gma,
                const float*  __restrict__ bta,
                const float*  __restrict__ rmean,
                const float*  __restrict__ rvar,
                float* __restrict__ out, int N)
{
    constexpr float VX = 0.16f, VY = 0.16f;
    constexpr float X_OFF = 0.08f;       // VX/2 + 0.0
    constexpr float Y_OFF = -39.6f;      // VY/2 + (-39.68)
    constexpr float BN_EPS = 1e-3f;

    // SoA staging: [warp][component][point]. Single buffer, 2 KB/block.
    __shared__ float sbuf[WARPS_PER_BLOCK][4][MPTS];

    const int lane = threadIdx.x & 31;
    const int warp = threadIdx.x >> 5;
    const int u0 = lane;
    const int u1 = lane + 32;

    // ---- fold weights + BN once per warp ----
    float wm4a, wm5a, wm6a, wm7a, wm8a, ba;
    float wm4b = 0.f, wm5b = 0.f, wm6b = 0.f, wm7b = 0.f, wm8b = 0.f, bb = 0.f;
    ull wsa0, wsa1, wsa2, wsa3;
    ull wsb0 = 0, wsb1 = 0, wsb2 = 0, wsb3 = 0;
    {
        const float inv = gma[u0] / sqrtf(rvar[u0] + BN_EPS);
        ba = bta[u0] - rmean[u0] * inv;
        const float* w = W + u0 * 9;
        wsa0 = dup2((w[0] + w[4] + w[7]) * inv);
        wsa1 = dup2((w[1] + w[5] + w[8]) * inv);
        wsa2 = dup2((w[2] + w[6]) * inv);
        wsa3 = dup2(w[3] * inv);
        wm4a = w[4] * inv; wm5a = w[5] * inv; wm6a = w[6] * inv;
        wm7a = w[7] * inv; wm8a = w[8] * inv;
    }
    if (u1 < 63) {
        const float inv = gma[u1] / sqrtf(rvar[u1] + BN_EPS);
        bb = bta[u1] - rmean[u1] * inv;
        const float* w = W + u1 * 9;
        wsb0 = dup2((w[0] + w[4] + w[7]) * inv);
        wsb1 = dup2((w[1] + w[5] + w[8]) * inv);
        wsb2 = dup2((w[2] + w[6]) * inv);
        wsb3 = dup2(w[3] * inv);
        wm4b = w[4] * inv; wm5b = w[5] * inv; wm6b = w[6] * inv;
        wm7b = w[7] * inv; wm8b = w[8] * inv;
    }

    const float nanv = __int_as_float(0x7fffffff);   // qNaN: dropped by fmaxf
    const int stride = gridDim.x * WARPS_PER_BLOCK;

    for (int n = blockIdx.x * WARPS_PER_BLOCK + warp; n < N; n += stride) {
        const float4 f = feats[(size_t)n * MPTS + lane];
        const int    np = num_points[n];     // warp-uniform
        const int4   cc = coors[n];

        // stage: padded slots get NaN so they vanish in the max (no predicates)
        const bool valid = lane < np;
        __syncwarp();                        // prior iteration's reads done
        sbuf[warp][0][lane] = valid ? f.x : nanv;
        sbuf[warp][1][lane] = valid ? f.y : nanv;
        sbuf[warp][2][lane] = valid ? f.z : nanv;
        sbuf[warp][3][lane] = valid ? f.w : nanv;

        // pillar xyz sum over ALL 32 raw points (reference sums unmasked);
        // packed x,y butterfly + scalar z. Off the inner-loop critical path.
        ull   sxy = pack2(f.x, f.y);
        float sz  = f.z;
        #pragma unroll
        for (int off = 16; off; off >>= 1) {
            sxy = add2(sxy, __shfl_xor_sync(0xffffffffu, sxy, off));
            sz += __shfl_xor_sync(0xffffffffu, sz, off);
        }
        const float2 sxyv = unpk(sxy);
        const float rnp = __fdividef(1.0f, (float)np);
        const float mx = sxyv.x * rnp, my = sxyv.y * rnp, mz = sz * rnp;
        const float ox = (float)cc.w * VX + X_OFF;
        const float oy = (float)cc.z * VY + Y_OFF;
        const float c0 = ba - (mx * wm4a + my * wm5a + mz * wm6a + ox * wm7a + oy * wm8a);
        const float c1 = bb - (mx * wm4b + my * wm5b + mz * wm6b + ox * wm7b + oy * wm8b);

        __syncwarp();                        // staging visible to all lanes

        const ulonglong2* X2 = (const ulonglong2*)sbuf[warp][0];
        const ulonglong2* Y2 = (const ulonglong2*)sbuf[warp][1];
        const ulonglong2* Z2 = (const ulonglong2*)sbuf[warp][2];
        const ulonglong2* W2 = (const ulonglong2*)sbuf[warp][3];

        float r0 = -INFINITY, r1 = -INFINITY;   // max of q only; +c at the end

        #pragma unroll
        for (int c = 0; c < MPTS / 4; ++c) {
            if (c == 0 || np > 4 * c) {          // warp-uniform branch
                const ulonglong2 X = X2[c];      // {x0,x1},{x2,x3} — LDS.128, imm offset
                const ulonglong2 Y = Y2[c];
                const ulonglong2 Z = Z2[c];
                const ulonglong2 Wv = W2[c];
                const ull qA0 = fma2(X.x, wsa0, fma2(Y.x, wsa1, fma2(Z.x, wsa2, mul2(Wv.x, wsa3))));
                const ull qA1 = fma2(X.y, wsa0, fma2(Y.y, wsa1, fma2(Z.y, wsa2, mul2(Wv.y, wsa3))));
                const ull qB0 = fma2(X.x, wsb0, fma2(Y.x, wsb1, fma2(Z.x, wsb2, mul2(Wv.x, wsb3))));
                const ull qB1 = fma2(X.y, wsb0, fma2(Y.y, wsb1, fma2(Z.y, wsb2, mul2(Wv.y, wsb3))));
                const float2 a0 = unpk(qA0), a1 = unpk(qA1);
                const float2 b0 = unpk(qB0), b1 = unpk(qB1);
                r0 = fmaxf(r0, fmaxf(fmaxf(a0.x, a0.y), fmaxf(a1.x, a1.y)));
                r1 = fmaxf(r1, fmaxf(fmaxf(b0.x, b0.y), fmaxf(b1.x, b1.y)));
            }
        }

        // add pillar constant; padded points contribute exactly the BN bias
        float d0 = r0 + c0;
        float d1 = r1 + c1;
        if (np < MPTS) { d0 = fmaxf(d0, ba); d1 = fmaxf(d1, bb); }

        float* o = out + (size_t)n * 64;
        o[u0] = fmaxf(d0, 0.0f);                 // relu(max) == max(relu)
        if (u1 < 63) o[u1] = fmaxf(d1, 0.0f);
        else         o[63] = (float)np;          // lane 31: num_points column
    }
}

extern "C" void kernel_launch(void* const* d_in, const int* in_sizes, int n_in,
                              void* d_out, int out_size)
{
    const float* features  = (const float*)d_in[0];
    const int*   num_pts   = (const int*)  d_in[1];
    const int*   coors     = (const int*)  d_in[2];
    const float* W         = (const float*)d_in[3];
    const float* gma       = (const float*)d_in[4];
    const float* bta       = (const float*)d_in[5];
    const float* rmean     = (const float*)d_in[6];
    const float* rvar      = (const float*)d_in[7];

    int N = in_sizes[1];                     // num_points element count == N pillars
    if (N <= 0 || N != in_sizes[0] / (MPTS * 4)) {
        N = in_sizes[0] / (MPTS * 4);        // defensive fallback
    }

    pfn_kernel<<<GRID_BLOCKS, THREADS>>>(
        (const float4*)features, num_pts, (const int4*)coors,
        W, gma, bta, rmean, rvar, (float*)d_out, N);
}

// round 9
// speedup vs baseline: 1.0971x; 1.0392x over previous
#include <cuda_runtime.h>
#include <math.h>

// PillarFeatureNet fused kernel — R9: +occupancy (wm in shared, launch_bounds 9),
// next-pillar prefetch, packed per-pillar constants, paired float2 output store.
// features: (N, 32, 4) f32; num_points: (N,) i32; coors: (N,4) i32 [b,z,cy,cx]
// W: (63,9) f32; gamma/beta/running_mean/running_var: (63,) f32
// out: (N, 64) f32  = [max over points of relu(BN(feats@W^T)) | num_points]

#define MPTS 32
#define WARPS_PER_BLOCK 4
#define THREADS (WARPS_PER_BLOCK * 32)
#define GRID_BLOCKS 1332   // 148 SMs * 9 CTAs

typedef unsigned long long ull;

__device__ __forceinline__ ull fma2(ull a, ull b, ull c) {
    ull d; asm("fma.rn.f32x2 %0,%1,%2,%3;" : "=l"(d) : "l"(a), "l"(b), "l"(c)); return d;
}
__device__ __forceinline__ ull mul2(ull a, ull b) {
    ull d; asm("mul.rn.f32x2 %0,%1,%2;" : "=l"(d) : "l"(a), "l"(b)); return d;
}
__device__ __forceinline__ ull add2(ull a, ull b) {
    ull d; asm("add.rn.f32x2 %0,%1,%2;" : "=l"(d) : "l"(a), "l"(b)); return d;
}
__device__ __forceinline__ ull sub2(ull a, ull b) {
    ull d; asm("sub.rn.f32x2 %0,%1,%2;" : "=l"(d) : "l"(a), "l"(b)); return d;
}
__device__ __forceinline__ ull dup2(float v) {
    ull d; asm("mov.b64 %0,{%1,%1};" : "=l"(d) : "f"(v)); return d;
}
__device__ __forceinline__ ull pack2(float lo, float hi) {
    ull d; asm("mov.b64 %0,{%1,%2};" : "=l"(d) : "f"(lo), "f"(hi)); return d;
}
__device__ __forceinline__ float2 unpk(ull p) {
    float lo, hi; asm("mov.b64 {%0,%1},%2;" : "=f"(lo), "=f"(hi) : "l"(p));
    return make_float2(lo, hi);
}

__global__ __launch_bounds__(THREADS, 9)
void pfn_kernel(const float4* __restrict__ feats,
                const int*    __restrict__ num_points,
                const int*    __restrict__ coors,      // (N,4) ints, we use [2],[3]
                const float*  __restrict__ W,
                const float*  __restrict__ gma,
                const float*  __restrict__ bta,
                const float*  __restrict__ rmean,
                const float*  __restrict__ rvar,
                float* __restrict__ out, int N)
{
    constexpr float VX = 0.16f, VY = 0.16f;
    constexpr float X_OFF = 0.08f;       // VX/2 + 0.0
    constexpr float Y_OFF = -39.6f;      // VY/2 + (-39.68)
    constexpr float BN_EPS = 1e-3f;

    // SoA point staging per warp (2 KB) + block-shared wm table (1.25 KB).
    __shared__ float  sbuf[WARPS_PER_BLOCK][4][MPTS];
    __shared__ float2 swm[5][32];        // swm[k][lane] = {wm_k(2*lane), wm_k(2*lane+1)}

    const int lane = threadIdx.x & 31;
    const int warp = threadIdx.x >> 5;
    const int uA = 2 * lane;             // output columns uA, uA+1 (lane31: 62, [63]=np)
    const bool haveB = (uA + 1) < 63;

    // ---- fold weights + BN: ws (4-term packed) in regs, wm (5-term) in shared ----
    ull wsa0, wsa1, wsa2, wsa3;
    ull wsb0 = 0, wsb1 = 0, wsb2 = 0, wsb3 = 0;
    float ba, bb = 0.f;
    {
        const float inv = gma[uA] * rsqrtf(rvar[uA] + BN_EPS);
        ba = bta[uA] - rmean[uA] * inv;
        const float* w = W + uA * 9;
        wsa0 = dup2((w[0] + w[4] + w[7]) * inv);
        wsa1 = dup2((w[1] + w[5] + w[8]) * inv);
        wsa2 = dup2((w[2] + w[6]) * inv);
        wsa3 = dup2(w[3] * inv);
        if (warp == 0) {
            #pragma unroll
            for (int k = 0; k < 5; ++k) swm[k][lane].x = w[4 + k] * inv;
        }
    }
    if (haveB) {
        const int uB = uA + 1;
        const float inv = gma[uB] * rsqrtf(rvar[uB] + BN_EPS);
        bb = bta[uB] - rmean[uB] * inv;
        const float* w = W + uB * 9;
        wsb0 = dup2((w[0] + w[4] + w[7]) * inv);
        wsb1 = dup2((w[1] + w[5] + w[8]) * inv);
        wsb2 = dup2((w[2] + w[6]) * inv);
        wsb3 = dup2(w[3] * inv);
        if (warp == 0) {
            #pragma unroll
            for (int k = 0; k < 5; ++k) swm[k][lane].y = w[4 + k] * inv;
        }
    } else if (warp == 0) {
        #pragma unroll
        for (int k = 0; k < 5; ++k) swm[k][lane].y = 0.f;
    }
    const ull bap = pack2(ba, bb);
    __syncthreads();                     // wm table visible to all warps

    const float nanv = __int_as_float(0x7fffffff);   // qNaN: dropped by fmaxf
    const int stride = gridDim.x * WARPS_PER_BLOCK;

    int n = blockIdx.x * WARPS_PER_BLOCK + warp;
    if (n >= N) return;

    // ---- prime the pipeline ----
    float4 f  = __ldcs(&feats[(size_t)n * MPTS + lane]);
    int    np = num_points[n];
    int2   cz = *(const int2*)(coors + (size_t)n * 4 + 2);   // {cy, cx}

    while (true) {
        const int n_next = n + stride;
        const bool have_next = (n_next < N);

        __syncwarp();                    // prior iteration's reads done
        const bool valid = lane < np;
        sbuf[warp][0][lane] = valid ? f.x : nanv;
        sbuf[warp][1][lane] = valid ? f.y : nanv;
        sbuf[warp][2][lane] = valid ? f.z : nanv;
        sbuf[warp][3][lane] = valid ? f.w : nanv;

        // prefetch next pillar — hides LDG latency under butterfly + inner loop
        float4 f_nx; int np_nx = 1; int2 cz_nx;
        if (have_next) {
            f_nx  = __ldcs(&feats[(size_t)n_next * MPTS + lane]);
            np_nx = num_points[n_next];
            cz_nx = *(const int2*)(coors + (size_t)n_next * 4 + 2);
        }

        // pillar xyz sum over ALL 32 raw points (reference sums unmasked)
        ull   sxy = pack2(f.x, f.y);
        float sz  = f.z;
        #pragma unroll
        for (int off = 16; off; off >>= 1) {
            sxy = add2(sxy, __shfl_xor_sync(0xffffffffu, sxy, off));
            sz += __shfl_xor_sync(0xffffffffu, sz, off);
        }
        const float2 sxyv = unpk(sxy);
        const float rnp = __fdividef(1.0f, (float)np);
        const float mx = sxyv.x * rnp, my = sxyv.y * rnp, mz = sz * rnp;
        const float ox = (float)cz.y * VX + X_OFF;
        const float oy = (float)cz.x * VY + Y_OFF;

        // packed per-pillar constant pair {c(uA), c(uA+1)}
        ull t = mul2(*(const ull*)&swm[0][lane], dup2(mx));
        t = fma2(*(const ull*)&swm[1][lane], dup2(my), t);
        t = fma2(*(const ull*)&swm[2][lane], dup2(mz), t);
        t = fma2(*(const ull*)&swm[3][lane], dup2(ox), t);
        t = fma2(*(const ull*)&swm[4][lane], dup2(oy), t);
        const float2 cp = unpk(sub2(bap, t));

        __syncwarp();                    // staging visible to all lanes

        const ulonglong2* X2 = (const ulonglong2*)sbuf[warp][0];
        const ulonglong2* Y2 = (const ulonglong2*)sbuf[warp][1];
        const ulonglong2* Z2 = (const ulonglong2*)sbuf[warp][2];
        const ulonglong2* W2 = (const ulonglong2*)sbuf[warp][3];

        float r0 = -INFINITY, r1 = -INFINITY;   // max of q only; +c at the end

        #pragma unroll
        for (int c = 0; c < MPTS / 4; ++c) {
            if (c == 0 || np > 4 * c) {          // warp-uniform branch
                const ulonglong2 X = X2[c];      // LDS.128, immediate offset
                const ulonglong2 Y = Y2[c];
                const ulonglong2 Z = Z2[c];
                const ulonglong2 Wv = W2[c];
                const ull qA0 = fma2(X.x, wsa0, fma2(Y.x, wsa1, fma2(Z.x, wsa2, mul2(Wv.x, wsa3))));
                const ull qA1 = fma2(X.y, wsa0, fma2(Y.y, wsa1, fma2(Z.y, wsa2, mul2(Wv.y, wsa3))));
                const ull qB0 = fma2(X.x, wsb0, fma2(Y.x, wsb1, fma2(Z.x, wsb2, mul2(Wv.x, wsb3))));
                const ull qB1 = fma2(X.y, wsb0, fma2(Y.y, wsb1, fma2(Z.y, wsb2, mul2(Wv.y, wsb3))));
                const float2 a0 = unpk(qA0), a1 = unpk(qA1);
                const float2 b0 = unpk(qB0), b1 = unpk(qB1);
                r0 = fmaxf(r0, fmaxf(fmaxf(a0.x, a0.y), fmaxf(a1.x, a1.y)));
                r1 = fmaxf(r1, fmaxf(fmaxf(b0.x, b0.y), fmaxf(b1.x, b1.y)));
            }
        }

        // add pillar constant; padded points contribute exactly the BN bias
        float d0 = r0 + cp.x;
        float d1 = r1 + cp.y;
        if (np < MPTS) { d0 = fmaxf(d0, ba); d1 = fmaxf(d1, bb); }

        float2 val;
        val.x = fmaxf(d0, 0.0f);                 // relu(max) == max(relu)
        val.y = haveB ? fmaxf(d1, 0.0f) : (float)np;   // lane 31: num_points column
        __stcs((float2*)out + (size_t)n * 32 + lane, val);   // one STG.64, 256B/warp

        if (!have_next) break;
        n = n_next; f = f_nx; np = np_nx; cz = cz_nx;
    }
}

extern "C" void kernel_launch(void* const* d_in, const int* in_sizes, int n_in,
                              void* d_out, int out_size)
{
    const float* features  = (const float*)d_in[0];
    const int*   num_pts   = (const int*)  d_in[1];
    const int*   coors     = (const int*)  d_in[2];
    const float* W         = (const float*)d_in[3];
    const float* gma       = (const float*)d_in[4];
    const float* bta       = (const float*)d_in[5];
    const float* rmean     = (const float*)d_in[6];
    const float* rvar      = (const float*)d_in[7];

    int N = in_sizes[1];                     // num_points element count == N pillars
    if (N <= 0 || N != in_sizes[0] / (MPTS * 4)) {
        N = in_sizes[0] / (MPTS * 4);        // defensive fallback
    }

    pfn_kernel<<<GRID_BLOCKS, THREADS>>>(
        (const float4*)features, num_pts, coors,
        W, gma, bta, rmean, rvar, (float*)d_out, N);
}

// round 11
// speedup vs baseline: 1.1473x; 1.0457x over previous
#include <cuda_runtime.h>
#include <math.h>

// PillarFeatureNet fused — R10: two pillars per warp iteration (packed butterfly,
// amortized syncs/staging/loop), register-neutral prefetch, f32x2 math throughout.
// features: (N, 32, 4) f32; num_points: (N,) i32; coors: (N,4) i32 [b,z,cy,cx]
// W: (63,9) f32; gamma/beta/rm/rv: (63,) f32
// out: (N, 64) f32 = [max over points of relu(BN(feats@W^T)) | num_points]

#define MPTS 32
#define WARPS_PER_BLOCK 4
#define THREADS (WARPS_PER_BLOCK * 32)
#define GRID_BLOCKS 1184   // 148 SMs * 8 CTAs

typedef unsigned long long ull;

__device__ __forceinline__ ull fma2(ull a, ull b, ull c) {
    ull d; asm("fma.rn.f32x2 %0,%1,%2,%3;" : "=l"(d) : "l"(a), "l"(b), "l"(c)); return d;
}
__device__ __forceinline__ ull mul2(ull a, ull b) {
    ull d; asm("mul.rn.f32x2 %0,%1,%2;" : "=l"(d) : "l"(a), "l"(b)); return d;
}
__device__ __forceinline__ ull add2(ull a, ull b) {
    ull d; asm("add.rn.f32x2 %0,%1,%2;" : "=l"(d) : "l"(a), "l"(b)); return d;
}
__device__ __forceinline__ ull sub2(ull a, ull b) {
    ull d; asm("sub.rn.f32x2 %0,%1,%2;" : "=l"(d) : "l"(a), "l"(b)); return d;
}
__device__ __forceinline__ ull dup2(float v) {
    ull d; asm("mov.b64 %0,{%1,%1};" : "=l"(d) : "f"(v)); return d;
}
__device__ __forceinline__ ull pack2(float lo, float hi) {
    ull d; asm("mov.b64 %0,{%1,%2};" : "=l"(d) : "f"(lo), "f"(hi)); return d;
}
__device__ __forceinline__ float2 unpk(ull p) {
    float lo, hi; asm("mov.b64 {%0,%1},%2;" : "=f"(lo), "=f"(hi) : "l"(p));
    return make_float2(lo, hi);
}
__device__ __forceinline__ ull shfl_xor64(ull v, int off) {
    float2 t = unpk(v);
    t.x = __shfl_xor_sync(0xffffffffu, t.x, off);
    t.y = __shfl_xor_sync(0xffffffffu, t.y, off);
    return pack2(t.x, t.y);
}

__global__ __launch_bounds__(THREADS, 8)
void pfn_kernel(const float4* __restrict__ feats,
                const int*    __restrict__ num_points,
                const int*    __restrict__ coors,      // (N,4) ints; use [2]=cy,[3]=cx
                const float*  __restrict__ W,
                const float*  __restrict__ gma,
                const float*  __restrict__ bta,
                const float*  __restrict__ rmean,
                const float*  __restrict__ rvar,
                float* __restrict__ out, int N)
{
    constexpr float VX = 0.16f, VY = 0.16f;
    constexpr float X_OFF = 0.08f;       // VX/2 + 0.0
    constexpr float Y_OFF = -39.6f;      // VY/2 + (-39.68)
    constexpr float BN_EPS = 1e-3f;

    // Per-warp SoA staging for TWO pillars (4 KB/block) + wm table (1.25 KB).
    __shared__ float  sbuf[WARPS_PER_BLOCK][4][2][MPTS];
    __shared__ float2 swm[5][32];        // swm[k][lane] = {wm_k(2l), wm_k(2l+1)}

    const int lane = threadIdx.x & 31;
    const int warp = threadIdx.x >> 5;
    const int uA = 2 * lane;             // outputs uA, uA+1 (lane31: 62, col63=np)
    const bool haveB = (uA + 1) < 63;

    // ---- fold weights + BN (ws packed in regs; wm in shared) ----
    ull wsa0, wsa1, wsa2, wsa3;
    ull wsb0 = 0, wsb1 = 0, wsb2 = 0, wsb3 = 0;
    float ba, bb = 0.f;
    {
        const float inv = gma[uA] * rsqrtf(rvar[uA] + BN_EPS);
        ba = bta[uA] - rmean[uA] * inv;
        const float* w = W + uA * 9;
        wsa0 = dup2((w[0] + w[4] + w[7]) * inv);
        wsa1 = dup2((w[1] + w[5] + w[8]) * inv);
        wsa2 = dup2((w[2] + w[6]) * inv);
        wsa3 = dup2(w[3] * inv);
        if (warp == 0) {
            #pragma unroll
            for (int k = 0; k < 5; ++k) swm[k][lane].x = w[4 + k] * inv;
        }
    }
    if (haveB) {
        const int uB = uA + 1;
        const float inv = gma[uB] * rsqrtf(rvar[uB] + BN_EPS);
        bb = bta[uB] - rmean[uB] * inv;
        const float* w = W + uB * 9;
        wsb0 = dup2((w[0] + w[4] + w[7]) * inv);
        wsb1 = dup2((w[1] + w[5] + w[8]) * inv);
        wsb2 = dup2((w[2] + w[6]) * inv);
        wsb3 = dup2(w[3] * inv);
        if (warp == 0) {
            #pragma unroll
            for (int k = 0; k < 5; ++k) swm[k][lane].y = w[4 + k] * inv;
        }
    } else if (warp == 0) {
        #pragma unroll
        for (int k = 0; k < 5; ++k) swm[k][lane].y = 0.f;
    }
    const ull bap = pack2(ba, bb);
    __syncthreads();

    const float nanv = __int_as_float(0x7fffffff);   // qNaN: dropped by fmaxf
    const int gw = blockIdx.x * WARPS_PER_BLOCK + warp;   // global warp id
    const int nwarps = gridDim.x * WARPS_PER_BLOCK;
    const int pstride = 2 * nwarps;                        // pillar-pair stride

    int n0 = 2 * gw;                      // even base pillar of this pair
    if (n0 >= N) return;

    // ---- prime: load pair 0 ----
    bool have1 = (n0 + 1) < N;
    float4 f0 = __ldcs(&feats[(size_t)n0 * MPTS + lane]);
    float4 f1 = have1 ? __ldcs(&feats[(size_t)(n0 + 1) * MPTS + lane])
                      : make_float4(0.f, 0.f, 0.f, 0.f);
    int2 np01 = have1 ? *(const int2*)(num_points + n0)
                      : make_int2(num_points[n0], 1);
    int2 cz0 = *(const int2*)(coors + (size_t)n0 * 4 + 2);          // {cy,cx}
    int2 cz1 = have1 ? *(const int2*)(coors + (size_t)(n0 + 1) * 4 + 2) : make_int2(0, 0);

    while (true) {
        const int n_nx = n0 + pstride;
        const bool have_next = (n_nx < N);
        const int np0 = np01.x, np1 = np01.y;

        // packed cross-pillar butterfly: sums over ALL 32 raw points, both pillars
        ull X01 = pack2(f0.x, f1.x);
        ull Y01 = pack2(f0.y, f1.y);
        ull Z01 = pack2(f0.z, f1.z);
        #pragma unroll
        for (int off = 16; off; off >>= 1) {
            X01 = add2(X01, shfl_xor64(X01, off));
            Y01 = add2(Y01, shfl_xor64(Y01, off));
            Z01 = add2(Z01, shfl_xor64(Z01, off));
        }
        const float2 sx = unpk(X01), sy = unpk(Y01), sz = unpk(Z01);

        // stage both pillars (NaN in padded slots)
        __syncwarp();                    // prior iteration's reads done
        const bool v0 = lane < np0, v1 = lane < np1;
        sbuf[warp][0][0][lane] = v0 ? f0.x : nanv;
        sbuf[warp][1][0][lane] = v0 ? f0.y : nanv;
        sbuf[warp][2][0][lane] = v0 ? f0.z : nanv;
        sbuf[warp][3][0][lane] = v0 ? f0.w : nanv;
        sbuf[warp][0][1][lane] = v1 ? f1.x : nanv;
        sbuf[warp][1][1][lane] = v1 ? f1.y : nanv;
        sbuf[warp][2][1][lane] = v1 ? f1.z : nanv;
        sbuf[warp][3][1][lane] = v1 ? f1.w : nanv;

        // register-neutral prefetch: overwrite f0/f1 with NEXT pair's data
        int2 np_nx = make_int2(1, 1); int2 cz0_nx, cz1_nx; bool have1_nx = false;
        if (have_next) {
            have1_nx = (n_nx + 1) < N;
            f0 = __ldcs(&feats[(size_t)n_nx * MPTS + lane]);
            if (have1_nx) f1 = __ldcs(&feats[(size_t)(n_nx + 1) * MPTS + lane]);
            np_nx = have1_nx ? *(const int2*)(num_points + n_nx)
                             : make_int2(num_points[n_nx], 1);
            cz0_nx = *(const int2*)(coors + (size_t)n_nx * 4 + 2);
            cz1_nx = have1_nx ? *(const int2*)(coors + (size_t)(n_nx + 1) * 4 + 2)
                              : make_int2(0, 0);
        }

        // per-pillar packed constants {c(uA), c(uA+1)}
        const ull m0 = *(const ull*)&swm[0][lane];
        const ull m1 = *(const ull*)&swm[1][lane];
        const ull m2 = *(const ull*)&swm[2][lane];
        const ull m3 = *(const ull*)&swm[3][lane];
        const ull m4 = *(const ull*)&swm[4][lane];

        const float rnp0 = __fdividef(1.0f, (float)np0);
        ull t0 = mul2(m0, dup2(sx.x * rnp0));
        t0 = fma2(m1, dup2(sy.x * rnp0), t0);
        t0 = fma2(m2, dup2(sz.x * rnp0), t0);
        t0 = fma2(m3, dup2((float)cz0.y * VX + X_OFF), t0);
        t0 = fma2(m4, dup2((float)cz0.x * VY + Y_OFF), t0);
        const float2 cp0 = unpk(sub2(bap, t0));

        const float rnp1 = __fdividef(1.0f, (float)np1);
        ull t1 = mul2(m0, dup2(sx.y * rnp1));
        t1 = fma2(m1, dup2(sy.y * rnp1), t1);
        t1 = fma2(m2, dup2(sz.y * rnp1), t1);
        t1 = fma2(m3, dup2((float)cz1.y * VX + X_OFF), t1);
        t1 = fma2(m4, dup2((float)cz1.x * VY + Y_OFF), t1);
        const float2 cp1 = unpk(sub2(bap, t1));

        __syncwarp();                    // staging visible

        // ---- pillar 0 inner loop ----
        {
            const ulonglong2* X2 = (const ulonglong2*)sbuf[warp][0][0];
            const ulonglong2* Y2 = (const ulonglong2*)sbuf[warp][1][0];
            const ulonglong2* Z2 = (const ulonglong2*)sbuf[warp][2][0];
            const ulonglong2* W2 = (const ulonglong2*)sbuf[warp][3][0];
            float r0 = -INFINITY, r1 = -INFINITY;
            #pragma unroll
            for (int c = 0; c < MPTS / 4; ++c) {
                if (c == 0 || np0 > 4 * c) {
                    const ulonglong2 X = X2[c], Y = Y2[c], Z = Z2[c], Wv = W2[c];
                    const ull qA0 = fma2(X.x, wsa0, fma2(Y.x, wsa1, fma2(Z.x, wsa2, mul2(Wv.x, wsa3))));
                    const ull qA1 = fma2(X.y, wsa0, fma2(Y.y, wsa1, fma2(Z.y, wsa2, mul2(Wv.y, wsa3))));
                    const ull qB0 = fma2(X.x, wsb0, fma2(Y.x, wsb1, fma2(Z.x, wsb2, mul2(Wv.x, wsb3))));
                    const ull qB1 = fma2(X.y, wsb0, fma2(Y.y, wsb1, fma2(Z.y, wsb2, mul2(Wv.y, wsb3))));
                    const float2 a0 = unpk(qA0), a1 = unpk(qA1);
                    const float2 b0 = unpk(qB0), b1 = unpk(qB1);
                    r0 = fmaxf(r0, fmaxf(fmaxf(a0.x, a0.y), fmaxf(a1.x, a1.y)));
                    r1 = fmaxf(r1, fmaxf(fmaxf(b0.x, b0.y), fmaxf(b1.x, b1.y)));
                }
            }
            float d0 = r0 + cp0.x, d1 = r1 + cp0.y;
            if (np0 < MPTS) { d0 = fmaxf(d0, ba); d1 = fmaxf(d1, bb); }
            float2 val;
            val.x = fmaxf(d0, 0.0f);
            val.y = haveB ? fmaxf(d1, 0.0f) : (float)np0;
            __stcs((float2*)out + (size_t)n0 * 32 + lane, val);
        }

        // ---- pillar 1 inner loop ----
        if (have1) {
            const ulonglong2* X2 = (const ulonglong2*)sbuf[warp][0][1];
            const ulonglong2* Y2 = (const ulonglong2*)sbuf[warp][1][1];
            const ulonglong2* Z2 = (const ulonglong2*)sbuf[warp][2][1];
            const ulonglong2* W2 = (const ulonglong2*)sbuf[warp][3][1];
            float r0 = -INFINITY, r1 = -INFINITY;
            #pragma unroll
            for (int c = 0; c < MPTS / 4; ++c) {
                if (c == 0 || np1 > 4 * c) {
                    const ulonglong2 X = X2[c], Y = Y2[c], Z = Z2[c], Wv = W2[c];
                    const ull qA0 = fma2(X.x, wsa0, fma2(Y.x, wsa1, fma2(Z.x, wsa2, mul2(Wv.x, wsa3))));
                    const ull qA1 = fma2(X.y, wsa0, fma2(Y.y, wsa1, fma2(Z.y, wsa2, mul2(Wv.y, wsa3))));
                    const ull qB0 = fma2(X.x, wsb0, fma2(Y.x, wsb1, fma2(Z.x, wsb2, mul2(Wv.x, wsb3))));
                    const ull qB1 = fma2(X.y, wsb0, fma2(Y.y, wsb1, fma2(Z.y, wsb2, mul2(Wv.y, wsb3))));
                    const float2 a0 = unpk(qA0), a1 = unpk(qA1);
                    const float2 b0 = unpk(qB0), b1 = unpk(qB1);
                    r0 = fmaxf(r0, fmaxf(fmaxf(a0.x, a0.y), fmaxf(a1.x, a1.y)));
                    r1 = fmaxf(r1, fmaxf(fmaxf(b0.x, b0.y), fmaxf(b1.x, b1.y)));
                }
            }
            float d0 = r0 + cp1.x, d1 = r1 + cp1.y;
            if (np1 < MPTS) { d0 = fmaxf(d0, ba); d1 = fmaxf(d1, bb); }
            float2 val;
            val.x = fmaxf(d0, 0.0f);
            val.y = haveB ? fmaxf(d1, 0.0f) : (float)np1;
            __stcs((float2*)out + (size_t)(n0 + 1) * 32 + lane, val);
        }

        if (!have_next) break;
        n0 = n_nx; have1 = have1_nx; np01 = np_nx; cz0 = cz0_nx; cz1 = cz1_nx;
    }
}

extern "C" void kernel_launch(void* const* d_in, const int* in_sizes, int n_in,
                              void* d_out, int out_size)
{
    const float* features  = (const float*)d_in[0];
    const int*   num_pts   = (const int*)  d_in[1];
    const int*   coors     = (const int*)  d_in[2];
    const float* W         = (const float*)d_in[3];
    const float* gma       = (const float*)d_in[4];
    const float* bta       = (const float*)d_in[5];
    const float* rmean     = (const float*)d_in[6];
    const float* rvar      = (const float*)d_in[7];

    int N = in_sizes[1];                     // num_points element count == N pillars
    if (N <= 0 || N != in_sizes[0] / (MPTS * 4)) {
        N = in_sizes[0] / (MPTS * 4);        // defensive fallback
    }

    pfn_kernel<<<GRID_BLOCKS, THREADS>>>(
        (const float4*)features, num_pts, coors,
        W, gma, bta, rmean, rvar, (float*)d_out, N);
}